// round 1
// baseline (speedup 1.0000x reference)
#include <cuda_runtime.h>
#include <math.h>
#include <stdint.h>

// ---------------------------------------------------------------------------
// TrAISformer forward, fp32 baseline.
// B=64, T=256, D=768, H=12, HD=64, L=12, FFN=3072, OUT=302. M = B*T = 16384.
// ---------------------------------------------------------------------------

#define M_ROWS   16384
#define DMODEL   768
#define NHEAD    12
#define HDIM     64
#define NLAYER   12
#define DFF      3072
#define NOUT     302
#define SEQ      256

// Scratch (device globals -> no allocations). g_s is shared between the
// attention score matrix (768 * 256 * 256 = 50,331,648 floats) and the MLP
// intermediate (16384 * 3072 = 50,331,648 floats) -- identical size, disjoint
// lifetimes within a layer.
__device__ float g_h[M_ROWS * DMODEL];
__device__ float g_x[M_ROWS * DMODEL];
__device__ float g_q[M_ROWS * DMODEL];
__device__ float g_k[M_ROWS * DMODEL];
__device__ float g_v[M_ROWS * DMODEL];
__device__ float g_y[M_ROWS * DMODEL];
__device__ float g_s[50331648];

__device__ __forceinline__ float gelu_f(float v) {
    return 0.5f * v * (1.0f + erff(v * 0.70710678118654752f));
}

// ---------------------------------------------------------------------------
// Embedding: h[row,:] = concat(lat[i0], lon[i1], sog[i2], cog[i3]) + pos[t,:]
// ---------------------------------------------------------------------------
__global__ void embed_kernel(const int* __restrict__ idxs,
                             const float* __restrict__ lat,
                             const float* __restrict__ lon,
                             const float* __restrict__ sog,
                             const float* __restrict__ cog,
                             const float* __restrict__ pos) {
    int row = blockIdx.x;
    int tid = threadIdx.x;
    int t = row & (SEQ - 1);
#pragma unroll
    for (int e = 0; e < 3; e++) {
        int j = (e << 8) + tid;           // 0..767
        int seg = j / 192;
        int off = j - seg * 192;
        int id = idxs[row * 4 + seg];
        const float* tab = (seg == 0) ? lat : (seg == 1) ? lon : (seg == 2) ? sog : cog;
        g_h[(size_t)row * DMODEL + j] = tab[id * 192 + off] + pos[t * DMODEL + j];
    }
}

// ---------------------------------------------------------------------------
// LayerNorm: one block per row (768 elems, 256 threads x 3).
// ---------------------------------------------------------------------------
__global__ void ln_kernel(const float* __restrict__ in, float* __restrict__ out,
                          const float* __restrict__ gamma, const float* __restrict__ beta) {
    int row = blockIdx.x;
    int tid = threadIdx.x;
    const float* x = in + (size_t)row * DMODEL;
    float v0 = x[tid], v1 = x[tid + 256], v2 = x[tid + 512];

    __shared__ float red[8];
    __shared__ float s_mean, s_rstd;

    float s = v0 + v1 + v2;
#pragma unroll
    for (int o = 16; o; o >>= 1) s += __shfl_xor_sync(0xffffffffu, s, o);
    if ((tid & 31) == 0) red[tid >> 5] = s;
    __syncthreads();
    if (tid == 0) {
        float t = 0.f;
#pragma unroll
        for (int i = 0; i < 8; i++) t += red[i];
        s_mean = t * (1.0f / 768.0f);
    }
    __syncthreads();
    float m = s_mean;
    float d0 = v0 - m, d1 = v1 - m, d2 = v2 - m;
    float q = d0 * d0 + d1 * d1 + d2 * d2;
#pragma unroll
    for (int o = 16; o; o >>= 1) q += __shfl_xor_sync(0xffffffffu, q, o);
    if ((tid & 31) == 0) red[tid >> 5] = q;
    __syncthreads();
    if (tid == 0) {
        float t = 0.f;
#pragma unroll
        for (int i = 0; i < 8; i++) t += red[i];
        s_rstd = rsqrtf(t * (1.0f / 768.0f) + 1e-5f);
    }
    __syncthreads();
    float r = s_rstd;
    float* o_ = out + (size_t)row * DMODEL;
    o_[tid]       = d0 * r * gamma[tid]       + beta[tid];
    o_[tid + 256] = d1 * r * gamma[tid + 256] + beta[tid + 256];
    o_[tid + 512] = d2 * r * gamma[tid + 512] + beta[tid + 512];
}

// ---------------------------------------------------------------------------
// Generic SGEMM: C[M,N] = A[M,K] @ B[K,N] (+bias) with epilogue:
//   EPI=0: store (+bias)   EPI=1: gelu (+bias)   EPI=2: accumulate into C (+bias)
// 64x64 block tile, BK=16, 256 threads, 4x4 register tile per thread.
// M must be a multiple of 64 and K a multiple of 16 (always true here).
// ---------------------------------------------------------------------------
template <int EPI>
__global__ void sgemm_kernel(const float* __restrict__ A, const float* __restrict__ B,
                             const float* __restrict__ bias, float* __restrict__ C,
                             int M, int N, int K) {
    __shared__ float As[16][65];
    __shared__ float Bs[16][64];
    int tid = threadIdx.x;
    int tx = tid & 15, ty = tid >> 4;
    int row0 = blockIdx.y << 6, col0 = blockIdx.x << 6;
    float acc[4][4] = {};

    for (int k0 = 0; k0 < K; k0 += 16) {
#pragma unroll
        for (int i = tid; i < 1024; i += 256) {
            int r = i >> 4, c = i & 15;
            As[c][r] = A[(size_t)(row0 + r) * K + (k0 + c)];
        }
#pragma unroll
        for (int i = tid; i < 1024; i += 256) {
            int r = i >> 6, c = i & 63;
            int col = col0 + c;
            Bs[r][c] = (col < N) ? B[(size_t)(k0 + r) * N + col] : 0.f;
        }
        __syncthreads();
#pragma unroll
        for (int kk = 0; kk < 16; kk++) {
            float a[4], b[4];
#pragma unroll
            for (int i = 0; i < 4; i++) a[i] = As[kk][ty * 4 + i];
#pragma unroll
            for (int j = 0; j < 4; j++) b[j] = Bs[kk][tx * 4 + j];
#pragma unroll
            for (int i = 0; i < 4; i++)
#pragma unroll
                for (int j = 0; j < 4; j++) acc[i][j] += a[i] * b[j];
        }
        __syncthreads();
    }

#pragma unroll
    for (int i = 0; i < 4; i++) {
        int r = row0 + ty * 4 + i;
#pragma unroll
        for (int j = 0; j < 4; j++) {
            int col = col0 + tx * 4 + j;
            if (col < N) {
                float v = acc[i][j] + (bias ? bias[col] : 0.f);
                float* cp = &C[(size_t)r * N + col];
                if (EPI == 1) v = gelu_f(v);
                if (EPI == 2) v += *cp;
                *cp = v;
            }
        }
    }
}

// ---------------------------------------------------------------------------
// QK^T: S[bh, q, k] = scale * sum_d Q[b,q,h,d] * K[b,k,h,d]
// grid: (16 tiles [4q x 4k], 768 bh). Upper-triangle tiles skipped (softmax
// masks them, and AV truncates the k range, so stale data there is harmless).
// ---------------------------------------------------------------------------
__global__ void qk_kernel(const float* __restrict__ Q, const float* __restrict__ K,
                          float* __restrict__ S) {
    int tq = blockIdx.x >> 2, tk = blockIdx.x & 3;
    if (tk > tq) return;
    int bh = blockIdx.y;
    int b = bh / NHEAD, h = bh % NHEAD;
    const float* Qp = Q + (size_t)b * SEQ * DMODEL + h * HDIM;
    const float* Kp = K + (size_t)b * SEQ * DMODEL + h * HDIM;
    float* Sp = S + (size_t)bh * (SEQ * SEQ);

    __shared__ float As[16][65];
    __shared__ float Bs[16][65];
    int tid = threadIdx.x;
    int tx = tid & 15, ty = tid >> 4;
    int row0 = tq << 6, col0 = tk << 6;
    float acc[4][4] = {};

    for (int k0 = 0; k0 < HDIM; k0 += 16) {
#pragma unroll
        for (int i = tid; i < 1024; i += 256) {
            int r = i >> 4, c = i & 15;
            As[c][r] = Qp[(size_t)(row0 + r) * DMODEL + (k0 + c)];
        }
#pragma unroll
        for (int i = tid; i < 1024; i += 256) {
            int r = i & 15, c = i >> 4;
            Bs[r][c] = Kp[(size_t)(col0 + c) * DMODEL + (k0 + r)];
        }
        __syncthreads();
#pragma unroll
        for (int kk = 0; kk < 16; kk++) {
            float a[4], bb[4];
#pragma unroll
            for (int i = 0; i < 4; i++) a[i] = As[kk][ty * 4 + i];
#pragma unroll
            for (int j = 0; j < 4; j++) bb[j] = Bs[kk][tx * 4 + j];
#pragma unroll
            for (int i = 0; i < 4; i++)
#pragma unroll
                for (int j = 0; j < 4; j++) acc[i][j] += a[i] * bb[j];
        }
        __syncthreads();
    }

#pragma unroll
    for (int i = 0; i < 4; i++)
#pragma unroll
        for (int j = 0; j < 4; j++)
            Sp[(size_t)(row0 + ty * 4 + i) * SEQ + (col0 + tx * 4 + j)] = acc[i][j] * 0.125f;
}

// ---------------------------------------------------------------------------
// Causal softmax in place: one warp per (bh, q) row of 256.
// ---------------------------------------------------------------------------
__global__ void softmax_kernel(float* __restrict__ S) {
    int w = (blockIdx.x << 3) + (threadIdx.x >> 5);   // global row id, 0..196607
    int q = w & (SEQ - 1);
    float* row = S + (size_t)(w >> 8) * (SEQ * SEQ) + (size_t)q * SEQ;
    int lane = threadIdx.x & 31;

    float v[8];
    float mx = -1e30f;
#pragma unroll
    for (int kk = 0; kk < 8; kk++) {
        int k = (kk << 5) + lane;
        float s = (k <= q) ? row[k] : -1e30f;
        v[kk] = s;
        mx = fmaxf(mx, s);
    }
#pragma unroll
    for (int o = 16; o; o >>= 1) mx = fmaxf(mx, __shfl_xor_sync(0xffffffffu, mx, o));
    float sum = 0.f;
#pragma unroll
    for (int kk = 0; kk < 8; kk++) {
        float e = expf(v[kk] - mx);
        v[kk] = e;
        sum += e;
    }
#pragma unroll
    for (int o = 16; o; o >>= 1) sum += __shfl_xor_sync(0xffffffffu, sum, o);
    float inv = 1.0f / sum;
#pragma unroll
    for (int kk = 0; kk < 8; kk++) {
        int k = (kk << 5) + lane;
        row[k] = v[kk] * inv;   // masked entries: exp underflows to exact 0
    }
}

// ---------------------------------------------------------------------------
// AV: Y[b,q,h,:] = P[q,:] @ V[b,:,h,:]. grid: (4 q-tiles, 768 bh).
// Causal: probabilities for k > q are exactly 0, so k range is [0, row0+64).
// ---------------------------------------------------------------------------
__global__ void av_kernel(const float* __restrict__ S, const float* __restrict__ V,
                          float* __restrict__ Y) {
    int bh = blockIdx.y;
    int b = bh / NHEAD, h = bh % NHEAD;
    const float* Sp = S + (size_t)bh * (SEQ * SEQ);
    const float* Vp = V + (size_t)b * SEQ * DMODEL + h * HDIM;
    float* Yp = Y + (size_t)b * SEQ * DMODEL + h * HDIM;

    __shared__ float As[16][65];
    __shared__ float Bs[16][64];
    int tid = threadIdx.x;
    int tx = tid & 15, ty = tid >> 4;
    int row0 = blockIdx.x << 6;
    int kend = row0 + 64;       // causal truncation
    float acc[4][4] = {};

    for (int k0 = 0; k0 < kend; k0 += 16) {
#pragma unroll
        for (int i = tid; i < 1024; i += 256) {
            int r = i >> 4, c = i & 15;
            As[c][r] = Sp[(size_t)(row0 + r) * SEQ + (k0 + c)];
        }
#pragma unroll
        for (int i = tid; i < 1024; i += 256) {
            int r = i >> 6, c = i & 63;
            Bs[r][c] = Vp[(size_t)(k0 + r) * DMODEL + c];
        }
        __syncthreads();
#pragma unroll
        for (int kk = 0; kk < 16; kk++) {
            float a[4], bb[4];
#pragma unroll
            for (int i = 0; i < 4; i++) a[i] = As[kk][ty * 4 + i];
#pragma unroll
            for (int j = 0; j < 4; j++) bb[j] = Bs[kk][tx * 4 + j];
#pragma unroll
            for (int i = 0; i < 4; i++)
#pragma unroll
                for (int j = 0; j < 4; j++) acc[i][j] += a[i] * bb[j];
        }
        __syncthreads();
    }

#pragma unroll
    for (int i = 0; i < 4; i++)
#pragma unroll
        for (int j = 0; j < 4; j++)
            Yp[(size_t)(row0 + ty * 4 + i) * DMODEL + (tx * 4 + j)] = acc[i][j];
}

// ---------------------------------------------------------------------------
// Launch
// ---------------------------------------------------------------------------
extern "C" void kernel_launch(void* const* d_in, const int* in_sizes, int n_in,
                              void* d_out, int out_size) {
    const int*   idxs  = (const int*)  d_in[0];
    const float* lat   = (const float*)d_in[1];
    const float* lon   = (const float*)d_in[2];
    const float* sog   = (const float*)d_in[3];
    const float* cog   = (const float*)d_in[4];
    const float* pos   = (const float*)d_in[5];
    const float* ln1_g = (const float*)d_in[6];
    const float* ln1_b = (const float*)d_in[7];
    const float* ln2_g = (const float*)d_in[8];
    const float* ln2_b = (const float*)d_in[9];
    const float* Wq    = (const float*)d_in[10];
    const float* bq    = (const float*)d_in[11];
    const float* Wk    = (const float*)d_in[12];
    const float* bk    = (const float*)d_in[13];
    const float* Wv    = (const float*)d_in[14];
    const float* bv    = (const float*)d_in[15];
    const float* Wo    = (const float*)d_in[16];
    const float* bo    = (const float*)d_in[17];
    const float* W1    = (const float*)d_in[18];
    const float* b1    = (const float*)d_in[19];
    const float* W2    = (const float*)d_in[20];
    const float* b2    = (const float*)d_in[21];
    const float* lnf_g = (const float*)d_in[22];
    const float* lnf_b = (const float*)d_in[23];
    const float* Whead = (const float*)d_in[24];
    float* out = (float*)d_out;

    float *hb, *xb, *qb, *kb, *vb, *yb, *sb;
    cudaGetSymbolAddress((void**)&hb, g_h);
    cudaGetSymbolAddress((void**)&xb, g_x);
    cudaGetSymbolAddress((void**)&qb, g_q);
    cudaGetSymbolAddress((void**)&kb, g_k);
    cudaGetSymbolAddress((void**)&vb, g_v);
    cudaGetSymbolAddress((void**)&yb, g_y);
    cudaGetSymbolAddress((void**)&sb, g_s);

    const size_t DD = (size_t)DMODEL * DMODEL;   // 589824
    const size_t DF = (size_t)DMODEL * DFF;      // 2359296

    embed_kernel<<<M_ROWS, 256>>>(idxs, lat, lon, sog, cog, pos);

    dim3 gD(DMODEL / 64, M_ROWS / 64);   // (12, 256)
    dim3 gF(DFF / 64, M_ROWS / 64);      // (48, 256)
    dim3 gQK(16, NHEAD * 64);            // (16, 768)
    dim3 gAV(4, NHEAD * 64);             // (4, 768)
    dim3 gHead((NOUT + 63) / 64, M_ROWS / 64);   // (5, 256)

    for (int l = 0; l < NLAYER; l++) {
        // x = LN1(h)
        ln_kernel<<<M_ROWS, 256>>>(hb, xb, ln1_g + l * DMODEL, ln1_b + l * DMODEL);
        // q,k,v = x@W + b
        sgemm_kernel<0><<<gD, 256>>>(xb, Wq + l * DD, bq + l * DMODEL, qb, M_ROWS, DMODEL, DMODEL);
        sgemm_kernel<0><<<gD, 256>>>(xb, Wk + l * DD, bk + l * DMODEL, kb, M_ROWS, DMODEL, DMODEL);
        sgemm_kernel<0><<<gD, 256>>>(xb, Wv + l * DD, bv + l * DMODEL, vb, M_ROWS, DMODEL, DMODEL);
        // attention
        qk_kernel<<<gQK, 256>>>(qb, kb, sb);
        softmax_kernel<<<(NHEAD * 64 * SEQ) / 8, 256>>>(sb);
        av_kernel<<<gAV, 256>>>(sb, vb, yb);
        // h += y@Wo + bo
        sgemm_kernel<2><<<gD, 256>>>(yb, Wo + l * DD, bo + l * DMODEL, hb, M_ROWS, DMODEL, DMODEL);
        // x = LN2(h)
        ln_kernel<<<M_ROWS, 256>>>(hb, xb, ln2_g + l * DMODEL, ln2_b + l * DMODEL);
        // ff = gelu(x@W1 + b1);  h += ff@W2 + b2
        sgemm_kernel<1><<<gF, 256>>>(xb, W1 + l * DF, b1 + l * DFF, sb, M_ROWS, DFF, DMODEL);
        sgemm_kernel<2><<<gD, 256>>>(sb, W2 + l * DF, b2 + l * DMODEL, hb, M_ROWS, DMODEL, DFF);
    }

    // final LN + head (no bias)
    ln_kernel<<<M_ROWS, 256>>>(hb, xb, lnf_g, lnf_b);
    sgemm_kernel<0><<<gHead, 256>>>(xb, Whead, nullptr, out, M_ROWS, NOUT, DMODEL);
}

// round 2
// speedup vs baseline: 3.9889x; 3.9889x over previous
#include <cuda_runtime.h>
#include <math.h>
#include <stdint.h>

// ---------------------------------------------------------------------------
// TrAISformer forward. GEMMs on tensor cores (TF32 mma.sync), attention SIMT.
// B=64, T=256, D=768, H=12, HD=64, L=12, FFN=3072, OUT=302. M = B*T = 16384.
// ---------------------------------------------------------------------------

#define M_ROWS   16384
#define DMODEL   768
#define NHEAD    12
#define HDIM     64
#define NLAYER   12
#define DFF      3072
#define NOUT     302
#define SEQ      256

__device__ float g_h[M_ROWS * DMODEL];
__device__ float g_x[M_ROWS * DMODEL];
__device__ float g_q[M_ROWS * DMODEL];
__device__ float g_k[M_ROWS * DMODEL];
__device__ float g_v[M_ROWS * DMODEL];
__device__ float g_y[M_ROWS * DMODEL];
__device__ float g_s[50331648];

__device__ __forceinline__ float gelu_f(float v) {
    return 0.5f * v * (1.0f + erff(v * 0.70710678118654752f));
}

__device__ __forceinline__ uint32_t f2tf32(float x) {
    uint32_t u;
    asm("cvt.rna.tf32.f32 %0, %1;" : "=r"(u) : "f"(x));
    return u;
}

__device__ __forceinline__ void mma_tf32(float* c, const uint32_t* a, const uint32_t* b) {
    asm volatile(
        "mma.sync.aligned.m16n8k8.row.col.f32.tf32.tf32.f32 "
        "{%0,%1,%2,%3}, {%4,%5,%6,%7}, {%8,%9}, {%0,%1,%2,%3};\n"
        : "+f"(c[0]), "+f"(c[1]), "+f"(c[2]), "+f"(c[3])
        : "r"(a[0]), "r"(a[1]), "r"(a[2]), "r"(a[3]), "r"(b[0]), "r"(b[1]));
}

// ---------------------------------------------------------------------------
// Embedding
// ---------------------------------------------------------------------------
__global__ void embed_kernel(const int* __restrict__ idxs,
                             const float* __restrict__ lat,
                             const float* __restrict__ lon,
                             const float* __restrict__ sog,
                             const float* __restrict__ cog,
                             const float* __restrict__ pos) {
    int row = blockIdx.x;
    int tid = threadIdx.x;
    int t = row & (SEQ - 1);
#pragma unroll
    for (int e = 0; e < 3; e++) {
        int j = (e << 8) + tid;
        int seg = j / 192;
        int off = j - seg * 192;
        int id = idxs[row * 4 + seg];
        const float* tab = (seg == 0) ? lat : (seg == 1) ? lon : (seg == 2) ? sog : cog;
        g_h[(size_t)row * DMODEL + j] = tab[id * 192 + off] + pos[t * DMODEL + j];
    }
}

// ---------------------------------------------------------------------------
// LayerNorm: one block per row.
// ---------------------------------------------------------------------------
__global__ void ln_kernel(const float* __restrict__ in, float* __restrict__ out,
                          const float* __restrict__ gamma, const float* __restrict__ beta) {
    int row = blockIdx.x;
    int tid = threadIdx.x;
    const float* x = in + (size_t)row * DMODEL;
    float v0 = x[tid], v1 = x[tid + 256], v2 = x[tid + 512];

    __shared__ float red[8];
    __shared__ float s_mean, s_rstd;

    float s = v0 + v1 + v2;
#pragma unroll
    for (int o = 16; o; o >>= 1) s += __shfl_xor_sync(0xffffffffu, s, o);
    if ((tid & 31) == 0) red[tid >> 5] = s;
    __syncthreads();
    if (tid == 0) {
        float t = 0.f;
#pragma unroll
        for (int i = 0; i < 8; i++) t += red[i];
        s_mean = t * (1.0f / 768.0f);
    }
    __syncthreads();
    float m = s_mean;
    float d0 = v0 - m, d1 = v1 - m, d2 = v2 - m;
    float q = d0 * d0 + d1 * d1 + d2 * d2;
#pragma unroll
    for (int o = 16; o; o >>= 1) q += __shfl_xor_sync(0xffffffffu, q, o);
    if ((tid & 31) == 0) red[tid >> 5] = q;
    __syncthreads();
    if (tid == 0) {
        float t = 0.f;
#pragma unroll
        for (int i = 0; i < 8; i++) t += red[i];
        s_rstd = rsqrtf(t * (1.0f / 768.0f) + 1e-5f);
    }
    __syncthreads();
    float r = s_rstd;
    float* o_ = out + (size_t)row * DMODEL;
    o_[tid]       = d0 * r * gamma[tid]       + beta[tid];
    o_[tid + 256] = d1 * r * gamma[tid + 256] + beta[tid + 256];
    o_[tid + 512] = d2 * r * gamma[tid + 512] + beta[tid + 512];
}

// ---------------------------------------------------------------------------
// TF32 tensor-core GEMM: C[M,N] = A[M,K] @ B[K,N] (+bias), epilogues:
//   EPI=0: store   EPI=1: gelu   EPI=2: accumulate into C
// Block tile 128x128, BK=16, 256 threads (8 warps, 4x2), warp tile 32x64.
// Requires: M % 128 == 0, N % 128 == 0, K % 16 == 0.
// ---------------------------------------------------------------------------
template <int EPI>
__global__ void __launch_bounds__(256, 2)
tgemm_kernel(const float* __restrict__ A, const float* __restrict__ B,
             const float* __restrict__ bias, float* __restrict__ C,
             int M, int N, int K) {
    __shared__ float As[128][20];    // As[m][k], stride 20 floats (80B, 16B aligned)
    __shared__ float Bs[16][136];    // Bs[k][n], stride 136 floats (544B, 16B aligned)

    const int tid  = threadIdx.x;
    const int lane = tid & 31;
    const int warp = tid >> 5;
    const int wm = (warp & 3) << 5;   // warp row offset within block: 0,32,64,96
    const int wn = (warp >> 2) << 6;  // warp col offset: 0,64
    const int g  = lane >> 2;         // group id (0..7)
    const int cq = lane & 3;          // thread-in-group (0..3)

    const size_t row0 = (size_t)blockIdx.y * 128;
    const size_t col0 = (size_t)blockIdx.x * 128;

    // global-load addressing
    const int ar = tid >> 2;          // A row 0..63 (and +64)
    const int ac = (tid & 3) << 2;    // A col within BK: 0,4,8,12
    const int br = tid >> 5;          // B row 0..7 (and +8)
    const int bc = (tid & 31) << 2;   // B col 0..124

    const float* Ap = A + (row0 + ar) * K + ac;
    const float* Bp = B + col0 + bc;

    float acc[2][8][4];
#pragma unroll
    for (int i = 0; i < 2; i++)
#pragma unroll
        for (int j = 0; j < 8; j++)
#pragma unroll
            for (int k = 0; k < 4; k++) acc[i][j][k] = 0.f;

    float4 pa0, pa1, pb0, pb1;
    // prefetch first tile
    pa0 = *(const float4*)(Ap);
    pa1 = *(const float4*)(Ap + (size_t)64 * K);
    pb0 = *(const float4*)(Bp + (size_t)br * N);
    pb1 = *(const float4*)(Bp + (size_t)(br + 8) * N);

    for (int k0 = 0; k0 < K; k0 += 16) {
        // commit staged tile to smem
        *(float4*)&As[ar][ac]       = pa0;
        *(float4*)&As[ar + 64][ac]  = pa1;
        *(float4*)&Bs[br][bc]       = pb0;
        *(float4*)&Bs[br + 8][bc]   = pb1;
        __syncthreads();

        // prefetch next tile
        if (k0 + 16 < K) {
            pa0 = *(const float4*)(Ap + k0 + 16);
            pa1 = *(const float4*)(Ap + (size_t)64 * K + k0 + 16);
            pb0 = *(const float4*)(Bp + (size_t)(k0 + 16 + br) * N);
            pb1 = *(const float4*)(Bp + (size_t)(k0 + 16 + br + 8) * N);
        }

#pragma unroll
        for (int ks = 0; ks < 16; ks += 8) {
            uint32_t af[2][4];
#pragma unroll
            for (int mt = 0; mt < 2; mt++) {
                int m = wm + (mt << 4);
                af[mt][0] = f2tf32(As[m + g][ks + cq]);
                af[mt][1] = f2tf32(As[m + g + 8][ks + cq]);
                af[mt][2] = f2tf32(As[m + g][ks + cq + 4]);
                af[mt][3] = f2tf32(As[m + g + 8][ks + cq + 4]);
            }
#pragma unroll
            for (int nt = 0; nt < 8; nt++) {
                uint32_t bf[2];
                bf[0] = f2tf32(Bs[ks + cq][wn + (nt << 3) + g]);
                bf[1] = f2tf32(Bs[ks + cq + 4][wn + (nt << 3) + g]);
                mma_tf32(acc[0][nt], af[0], bf);
                mma_tf32(acc[1][nt], af[1], bf);
            }
        }
        __syncthreads();
    }

    // epilogue: c0:(r,c) c1:(r,c+1) c2:(r+8,c) c3:(r+8,c+1); r=g, c=2*cq
#pragma unroll
    for (int mt = 0; mt < 2; mt++) {
        size_t r_hi = row0 + wm + (mt << 4) + g;
#pragma unroll
        for (int nt = 0; nt < 8; nt++) {
            size_t cb = col0 + wn + (nt << 3) + (cq << 1);
            float bv0 = bias ? bias[cb] : 0.f;
            float bv1 = bias ? bias[cb + 1] : 0.f;
#pragma unroll
            for (int rr = 0; rr < 2; rr++) {
                size_t r = r_hi + rr * 8;
                float v0 = acc[mt][nt][rr * 2 + 0] + bv0;
                float v1 = acc[mt][nt][rr * 2 + 1] + bv1;
                float* cp = &C[r * N + cb];
                if (EPI == 1) { v0 = gelu_f(v0); v1 = gelu_f(v1); }
                if (EPI == 2) { v0 += cp[0]; v1 += cp[1]; }
                cp[0] = v0;
                cp[1] = v1;
            }
        }
    }
}

// ---------------------------------------------------------------------------
// SIMT SGEMM (kept for the head GEMM, N=302): 64x64 tile.
// ---------------------------------------------------------------------------
__global__ void sgemm_head_kernel(const float* __restrict__ A, const float* __restrict__ B,
                                  float* __restrict__ C, int M, int N, int K) {
    __shared__ float As[16][65];
    __shared__ float Bs[16][64];
    int tid = threadIdx.x;
    int tx = tid & 15, ty = tid >> 4;
    int row0 = blockIdx.y << 6, col0 = blockIdx.x << 6;
    float acc[4][4] = {};

    for (int k0 = 0; k0 < K; k0 += 16) {
#pragma unroll
        for (int i = tid; i < 1024; i += 256) {
            int r = i >> 4, c = i & 15;
            As[c][r] = A[(size_t)(row0 + r) * K + (k0 + c)];
        }
#pragma unroll
        for (int i = tid; i < 1024; i += 256) {
            int r = i >> 6, c = i & 63;
            int col = col0 + c;
            Bs[r][c] = (col < N) ? B[(size_t)(k0 + r) * N + col] : 0.f;
        }
        __syncthreads();
#pragma unroll
        for (int kk = 0; kk < 16; kk++) {
            float a[4], b[4];
#pragma unroll
            for (int i = 0; i < 4; i++) a[i] = As[kk][ty * 4 + i];
#pragma unroll
            for (int j = 0; j < 4; j++) b[j] = Bs[kk][tx * 4 + j];
#pragma unroll
            for (int i = 0; i < 4; i++)
#pragma unroll
                for (int j = 0; j < 4; j++) acc[i][j] += a[i] * b[j];
        }
        __syncthreads();
    }

#pragma unroll
    for (int i = 0; i < 4; i++) {
        int r = row0 + ty * 4 + i;
#pragma unroll
        for (int j = 0; j < 4; j++) {
            int col = col0 + tx * 4 + j;
            if (col < N) C[(size_t)r * N + col] = acc[i][j];
        }
    }
}

// ---------------------------------------------------------------------------
// QK^T (SIMT, causal tiles only)
// ---------------------------------------------------------------------------
__global__ void qk_kernel(const float* __restrict__ Q, const float* __restrict__ K,
                          float* __restrict__ S) {
    int tq = blockIdx.x >> 2, tk = blockIdx.x & 3;
    if (tk > tq) return;
    int bh = blockIdx.y;
    int b = bh / NHEAD, h = bh % NHEAD;
    const float* Qp = Q + (size_t)b * SEQ * DMODEL + h * HDIM;
    const float* Kp = K + (size_t)b * SEQ * DMODEL + h * HDIM;
    float* Sp = S + (size_t)bh * (SEQ * SEQ);

    __shared__ float As[16][65];
    __shared__ float Bs[16][65];
    int tid = threadIdx.x;
    int tx = tid & 15, ty = tid >> 4;
    int row0 = tq << 6, col0 = tk << 6;
    float acc[4][4] = {};

    for (int k0 = 0; k0 < HDIM; k0 += 16) {
#pragma unroll
        for (int i = tid; i < 1024; i += 256) {
            int r = i >> 4, c = i & 15;
            As[c][r] = Qp[(size_t)(row0 + r) * DMODEL + (k0 + c)];
        }
#pragma unroll
        for (int i = tid; i < 1024; i += 256) {
            int r = i & 15, c = i >> 4;
            Bs[r][c] = Kp[(size_t)(col0 + c) * DMODEL + (k0 + r)];
        }
        __syncthreads();
#pragma unroll
        for (int kk = 0; kk < 16; kk++) {
            float a[4], bb[4];
#pragma unroll
            for (int i = 0; i < 4; i++) a[i] = As[kk][ty * 4 + i];
#pragma unroll
            for (int j = 0; j < 4; j++) bb[j] = Bs[kk][tx * 4 + j];
#pragma unroll
            for (int i = 0; i < 4; i++)
#pragma unroll
                for (int j = 0; j < 4; j++) acc[i][j] += a[i] * bb[j];
        }
        __syncthreads();
    }

#pragma unroll
    for (int i = 0; i < 4; i++)
#pragma unroll
        for (int j = 0; j < 4; j++)
            Sp[(size_t)(row0 + ty * 4 + i) * SEQ + (col0 + tx * 4 + j)] = acc[i][j] * 0.125f;
}

// ---------------------------------------------------------------------------
// Causal softmax in place
// ---------------------------------------------------------------------------
__global__ void softmax_kernel(float* __restrict__ S) {
    int w = (blockIdx.x << 3) + (threadIdx.x >> 5);
    int q = w & (SEQ - 1);
    float* row = S + (size_t)(w >> 8) * (SEQ * SEQ) + (size_t)q * SEQ;
    int lane = threadIdx.x & 31;

    float v[8];
    float mx = -1e30f;
#pragma unroll
    for (int kk = 0; kk < 8; kk++) {
        int k = (kk << 5) + lane;
        float s = (k <= q) ? row[k] : -1e30f;
        v[kk] = s;
        mx = fmaxf(mx, s);
    }
#pragma unroll
    for (int o = 16; o; o >>= 1) mx = fmaxf(mx, __shfl_xor_sync(0xffffffffu, mx, o));
    float sum = 0.f;
#pragma unroll
    for (int kk = 0; kk < 8; kk++) {
        float e = expf(v[kk] - mx);
        v[kk] = e;
        sum += e;
    }
#pragma unroll
    for (int o = 16; o; o >>= 1) sum += __shfl_xor_sync(0xffffffffu, sum, o);
    float inv = 1.0f / sum;
#pragma unroll
    for (int kk = 0; kk < 8; kk++) {
        int k = (kk << 5) + lane;
        row[k] = v[kk] * inv;
    }
}

// ---------------------------------------------------------------------------
// AV (SIMT, causal k-truncation)
// ---------------------------------------------------------------------------
__global__ void av_kernel(const float* __restrict__ S, const float* __restrict__ V,
                          float* __restrict__ Y) {
    int bh = blockIdx.y;
    int b = bh / NHEAD, h = bh % NHEAD;
    const float* Sp = S + (size_t)bh * (SEQ * SEQ);
    const float* Vp = V + (size_t)b * SEQ * DMODEL + h * HDIM;
    float* Yp = Y + (size_t)b * SEQ * DMODEL + h * HDIM;

    __shared__ float As[16][65];
    __shared__ float Bs[16][64];
    int tid = threadIdx.x;
    int tx = tid & 15, ty = tid >> 4;
    int row0 = blockIdx.x << 6;
    int kend = row0 + 64;
    float acc[4][4] = {};

    for (int k0 = 0; k0 < kend; k0 += 16) {
#pragma unroll
        for (int i = tid; i < 1024; i += 256) {
            int r = i >> 4, c = i & 15;
            As[c][r] = Sp[(size_t)(row0 + r) * SEQ + (k0 + c)];
        }
#pragma unroll
        for (int i = tid; i < 1024; i += 256) {
            int r = i >> 6, c = i & 63;
            Bs[r][c] = Vp[(size_t)(k0 + r) * DMODEL + c];
        }
        __syncthreads();
#pragma unroll
        for (int kk = 0; kk < 16; kk++) {
            float a[4], bb[4];
#pragma unroll
            for (int i = 0; i < 4; i++) a[i] = As[kk][ty * 4 + i];
#pragma unroll
            for (int j = 0; j < 4; j++) bb[j] = Bs[kk][tx * 4 + j];
#pragma unroll
            for (int i = 0; i < 4; i++)
#pragma unroll
                for (int j = 0; j < 4; j++) acc[i][j] += a[i] * bb[j];
        }
        __syncthreads();
    }

#pragma unroll
    for (int i = 0; i < 4; i++)
#pragma unroll
        for (int j = 0; j < 4; j++)
            Yp[(size_t)(row0 + ty * 4 + i) * DMODEL + (tx * 4 + j)] = acc[i][j];
}

// ---------------------------------------------------------------------------
// Launch
// ---------------------------------------------------------------------------
extern "C" void kernel_launch(void* const* d_in, const int* in_sizes, int n_in,
                              void* d_out, int out_size) {
    const int*   idxs  = (const int*)  d_in[0];
    const float* lat   = (const float*)d_in[1];
    const float* lon   = (const float*)d_in[2];
    const float* sog   = (const float*)d_in[3];
    const float* cog   = (const float*)d_in[4];
    const float* pos   = (const float*)d_in[5];
    const float* ln1_g = (const float*)d_in[6];
    const float* ln1_b = (const float*)d_in[7];
    const float* ln2_g = (const float*)d_in[8];
    const float* ln2_b = (const float*)d_in[9];
    const float* Wq    = (const float*)d_in[10];
    const float* bq    = (const float*)d_in[11];
    const float* Wk    = (const float*)d_in[12];
    const float* bk    = (const float*)d_in[13];
    const float* Wv    = (const float*)d_in[14];
    const float* bv    = (const float*)d_in[15];
    const float* Wo    = (const float*)d_in[16];
    const float* bo    = (const float*)d_in[17];
    const float* W1    = (const float*)d_in[18];
    const float* b1    = (const float*)d_in[19];
    const float* W2    = (const float*)d_in[20];
    const float* b2    = (const float*)d_in[21];
    const float* lnf_g = (const float*)d_in[22];
    const float* lnf_b = (const float*)d_in[23];
    const float* Whead = (const float*)d_in[24];
    float* out = (float*)d_out;

    float *hb, *xb, *qb, *kb, *vb, *yb, *sb;
    cudaGetSymbolAddress((void**)&hb, g_h);
    cudaGetSymbolAddress((void**)&xb, g_x);
    cudaGetSymbolAddress((void**)&qb, g_q);
    cudaGetSymbolAddress((void**)&kb, g_k);
    cudaGetSymbolAddress((void**)&vb, g_v);
    cudaGetSymbolAddress((void**)&yb, g_y);
    cudaGetSymbolAddress((void**)&sb, g_s);

    const size_t DD = (size_t)DMODEL * DMODEL;
    const size_t DF = (size_t)DMODEL * DFF;

    embed_kernel<<<M_ROWS, 256>>>(idxs, lat, lon, sog, cog, pos);

    dim3 gD(DMODEL / 128, M_ROWS / 128);     // (6, 128)
    dim3 gF(DFF / 128, M_ROWS / 128);        // (24, 128)
    dim3 gQK(16, NHEAD * 64);
    dim3 gAV(4, NHEAD * 64);
    dim3 gHead((NOUT + 63) / 64, M_ROWS / 64);

    for (int l = 0; l < NLAYER; l++) {
        ln_kernel<<<M_ROWS, 256>>>(hb, xb, ln1_g + l * DMODEL, ln1_b + l * DMODEL);
        tgemm_kernel<0><<<gD, 256>>>(xb, Wq + l * DD, bq + l * DMODEL, qb, M_ROWS, DMODEL, DMODEL);
        tgemm_kernel<0><<<gD, 256>>>(xb, Wk + l * DD, bk + l * DMODEL, kb, M_ROWS, DMODEL, DMODEL);
        tgemm_kernel<0><<<gD, 256>>>(xb, Wv + l * DD, bv + l * DMODEL, vb, M_ROWS, DMODEL, DMODEL);
        qk_kernel<<<gQK, 256>>>(qb, kb, sb);
        softmax_kernel<<<(NHEAD * 64 * SEQ) / 8, 256>>>(sb);
        av_kernel<<<gAV, 256>>>(sb, vb, yb);
        tgemm_kernel<2><<<gD, 256>>>(yb, Wo + l * DD, bo + l * DMODEL, hb, M_ROWS, DMODEL, DMODEL);
        ln_kernel<<<M_ROWS, 256>>>(hb, xb, ln2_g + l * DMODEL, ln2_b + l * DMODEL);
        tgemm_kernel<1><<<gF, 256>>>(xb, W1 + l * DF, b1 + l * DFF, sb, M_ROWS, DFF, DMODEL);
        tgemm_kernel<2><<<gD, 256>>>(sb, W2 + l * DF, b2 + l * DMODEL, hb, M_ROWS, DMODEL, DFF);
    }

    ln_kernel<<<M_ROWS, 256>>>(hb, xb, lnf_g, lnf_b);
    sgemm_head_kernel<<<gHead, 256>>>(xb, Whead, out, M_ROWS, NOUT, DMODEL);
}